// round 3
// baseline (speedup 1.0000x reference)
#include <cuda_runtime.h>
#include <math.h>

#define NN   200000
#define MM   12
#define FF   64
#define NBR  41
#define NBO  48           // padded output dim for edge MLP (zero w2 on pad)
#define NPR  24           // NBO/2 f32x2 pairs
#define ORIG 92
#define BB   2000
#define SHH  9
#define NC   3
#define HF   128
#define NM   (NN*MM)
#define NPB  (NN/BB)      // 100 atoms per crystal
#define APB  128          // atoms per conv block
#define EPB  128          // edges per edge block
#define ESTR 132          // padded edge-tile row stride (floats)
// folded: c0 * alpha * (1/M)
#define WSCALE (0.28209479177387814f * 0.125f / 12.0f)

typedef unsigned long long ull;

// scratch (allocation-free rule: __device__ globals)
__device__ float g_x[(size_t)NN * FF];       // 51.2 MB
__device__ float g_y[(size_t)NN * FF];       // 51.2 MB
__device__ float g_w[(size_t)NC * NM];       // 28.8 MB

__device__ __forceinline__ float softplusf(float t) {
    return fmaxf(t, 0.0f) + log1pf(__expf(-fabsf(t)));
}

// ---- packed fp32x2 helpers (SASS FFMA2; ptxas won't emit these itself) ----
__device__ __forceinline__ ull pack2(float lo, float hi) {
    ull r; asm("mov.b64 %0, {%1, %2};" : "=l"(r) : "f"(lo), "f"(hi)); return r;
}
__device__ __forceinline__ void unpack2(ull v, float& lo, float& hi) {
    asm("mov.b64 {%0, %1}, %2;" : "=f"(lo), "=f"(hi) : "l"(v));
}
__device__ __forceinline__ ull fma2(ull a, ull b, ull c) {
    ull d; asm("fma.rn.f32x2 %0, %1, %2, %3;" : "=l"(d) : "l"(a), "l"(b), "l"(c));
    return d;
}

// ---------------------------------------------------------------------------
// 1) x = atom_fea @ W_emb + b_emb      (200000 x 92) @ (92 x 64)
// ---------------------------------------------------------------------------
__global__ __launch_bounds__(256) void embed_kernel(
    const float* __restrict__ af, const float* __restrict__ W,
    const float* __restrict__ b)
{
    __shared__ float sW[ORIG][FF];
    __shared__ float sb[FF];
    for (int i = threadIdx.x; i < ORIG * FF; i += 256) sW[i >> 6][i & 63] = W[i];
    if (threadIdx.x < FF) sb[threadIdx.x] = b[threadIdx.x];
    __syncthreads();

    int a  = blockIdx.x * 16 + (threadIdx.x >> 4);
    int f0 = (threadIdx.x & 15) * 4;
    if (a >= NN) return;

    const float4* row4 = (const float4*)(af + (size_t)a * ORIG);
    ull acc0 = pack2(sb[f0], sb[f0 + 1]);
    ull acc1 = pack2(sb[f0 + 2], sb[f0 + 3]);
    #pragma unroll
    for (int k4 = 0; k4 < ORIG / 4; k4++) {
        float4 v = row4[k4];
        int k = k4 * 4;
        #pragma unroll
        for (int c = 0; c < 4; c++) {
            float vc = (c == 0) ? v.x : (c == 1) ? v.y : (c == 2) ? v.z : v.w;
            ull v2 = pack2(vc, vc);
            const ull* wr = (const ull*)&sW[k + c][f0];
            acc0 = fma2(v2, wr[0], acc0);
            acc1 = fma2(v2, wr[1], acc1);
        }
    }
    float4 o;
    unpack2(acc0, o.x, o.y);
    unpack2(acc1, o.z, o.w);
    *(float4*)&g_x[(size_t)a * FF + f0] = o;
}

// ---------------------------------------------------------------------------
// 2) Edge radial scalars, GEMM-style register tiling.
//    Block: 128 edges, 256 threads = 8 warps (warp = output group of 6).
//    Thread tile: 4 edges x 3 f32x2 output-pairs. e tile staged transposed
//    in smem and reused across all 3 layers; per-layer weights reloaded.
// ---------------------------------------------------------------------------
__global__ __launch_bounds__(256) void edge_kernel(
    const float* __restrict__ nbr_fea,
    const float* __restrict__ Wr1, const float* __restrict__ br1,
    const float* __restrict__ Wr2, const float* __restrict__ br2)
{
    __shared__ float e_s[NBR][ESTR];   // 21.6 KB, transposed edge tile
    __shared__ ull   w1_s[NBR][NPR];   // 7.9 KB, current layer W1 pairs
    __shared__ ull   b1_s[NPR];
    __shared__ float w2_s[NBO];
    __shared__ float b2_s;
    __shared__ float red[EPB][9];      // 4.6 KB, cross-warp partials

    const int t    = threadIdx.x;
    const int og   = t >> 5;           // 0..7: pairs og*3 .. og*3+2
    const int eg   = t & 31;           // edge group
    const int e0   = eg * 4;
    const size_t base = (size_t)blockIdx.x * EPB;

    // ---- stage e tile transposed (once, reused by all 3 layers) ----
    const float* eg_ptr = nbr_fea + base * NBR;
    for (int idx = t; idx < EPB * NBR; idx += 256) {
        int le = idx / NBR;
        int k  = idx - le * NBR;
        e_s[k][le] = __ldg(&eg_ptr[idx]);
    }

    #pragma unroll 1
    for (int l = 0; l < NC; l++) {
        __syncthreads();   // prev layer's k-loop/epilogue done before w reload

        // ---- load layer-l weights ----
        const float* W1l = Wr1 + (size_t)l * NBR * NBR;
        for (int idx = t; idx < NBR * NPR; idx += 256) {
            int k = idx / NPR, j = idx - k * NPR;
            int j2 = 2 * j;
            float lo = (j2     < NBR) ? __ldg(&W1l[k * NBR + j2])     : 0.f;
            float hi = (j2 + 1 < NBR) ? __ldg(&W1l[k * NBR + j2 + 1]) : 0.f;
            w1_s[k][j] = pack2(lo, hi);
        }
        if (t < NPR) {
            int j2 = 2 * t;
            float lo = (j2     < NBR) ? __ldg(&br1[l * NBR + j2])     : 0.f;
            float hi = (j2 + 1 < NBR) ? __ldg(&br1[l * NBR + j2 + 1]) : 0.f;
            b1_s[t] = pack2(lo, hi);
        }
        if (t < NBO)
            w2_s[t] = (t < NBR) ? __ldg(&Wr2[((size_t)l * NBR + t) * SHH]) : 0.f;
        if (t == 0) b2_s = __ldg(&br2[l * SHH]);
        __syncthreads();

        // ---- k-loop: acc[edge i][pair p] ----
        ull acc[4][3];
        {
            ull b0 = b1_s[og * 3], b1 = b1_s[og * 3 + 1], b2 = b1_s[og * 3 + 2];
            #pragma unroll
            for (int i = 0; i < 4; i++) { acc[i][0] = b0; acc[i][1] = b1; acc[i][2] = b2; }
        }

        #pragma unroll 4
        for (int k = 0; k < NBR; k++) {
            float4 av = *(const float4*)&e_s[k][e0];
            ull bw0 = w1_s[k][og * 3];
            ull bw1 = w1_s[k][og * 3 + 1];
            ull bw2 = w1_s[k][og * 3 + 2];
            ull a2;
            a2 = pack2(av.x, av.x);
            acc[0][0] = fma2(a2, bw0, acc[0][0]);
            acc[0][1] = fma2(a2, bw1, acc[0][1]);
            acc[0][2] = fma2(a2, bw2, acc[0][2]);
            a2 = pack2(av.y, av.y);
            acc[1][0] = fma2(a2, bw0, acc[1][0]);
            acc[1][1] = fma2(a2, bw1, acc[1][1]);
            acc[1][2] = fma2(a2, bw2, acc[1][2]);
            a2 = pack2(av.z, av.z);
            acc[2][0] = fma2(a2, bw0, acc[2][0]);
            acc[2][1] = fma2(a2, bw1, acc[2][1]);
            acc[2][2] = fma2(a2, bw2, acc[2][2]);
            a2 = pack2(av.w, av.w);
            acc[3][0] = fma2(a2, bw0, acc[3][0]);
            acc[3][1] = fma2(a2, bw1, acc[3][1]);
            acc[3][2] = fma2(a2, bw2, acc[3][2]);
        }

        // ---- epilogue: softplus . w2 partial, per thread ----
        float w2a = w2_s[og * 6],     w2b = w2_s[og * 6 + 1];
        float w2c = w2_s[og * 6 + 2], w2d = w2_s[og * 6 + 3];
        float w2e = w2_s[og * 6 + 4], w2f = w2_s[og * 6 + 5];
        #pragma unroll
        for (int i = 0; i < 4; i++) {
            float lo, hi, s;
            unpack2(acc[i][0], lo, hi);
            s  = softplusf(lo) * w2a + softplusf(hi) * w2b;
            unpack2(acc[i][1], lo, hi);
            s += softplusf(lo) * w2c + softplusf(hi) * w2d;
            unpack2(acc[i][2], lo, hi);
            s += softplusf(lo) * w2e + softplusf(hi) * w2f;
            red[e0 + i][og] = s;
        }
        __syncthreads();

        // ---- cross-warp reduce, one thread per edge ----
        if (t < EPB) {
            float s = b2_s;
            #pragma unroll
            for (int o = 0; o < 8; o++) s += red[t][o];
            g_w[(size_t)l * NM + base + t] = s * WSCALE;
        }
    }
}

// ---------------------------------------------------------------------------
// 3) Fused conv layer: y = weighted gather of xin, xout = y @ Wtp[l]
// ---------------------------------------------------------------------------
__global__ __launch_bounds__(256) void conv_kernel(
    const int* __restrict__ nbr_idx, const float* __restrict__ Wtp_l,
    const float* __restrict__ wl,
    const float* __restrict__ xin, float* __restrict__ xout)
{
    __shared__ float y_s[APB][68];
    __shared__ float sW[FF][FF];

    int t = threadIdx.x;
    for (int i = t; i < FF * FF; i += 256) sW[i >> 6][i & 63] = Wtp_l[i];

    int base = blockIdx.x * APB;
    int fg = t & 7;
    int f0 = fg * 8;

    #pragma unroll 1
    for (int r = 0; r < 4; r++) {
        int la = (t >> 3) + r * 32;
        int a  = base + la;
        float4 a0 = make_float4(0.f, 0.f, 0.f, 0.f);
        float4 a1 = make_float4(0.f, 0.f, 0.f, 0.f);
        if (a < NN) {
            #pragma unroll
            for (int j = 0; j < MM; j++) {
                int   s  = __ldg(&nbr_idx[a * MM + j]);
                float wj = __ldg(&wl[a * MM + j]);
                const float4* xr = (const float4*)(xin + (size_t)s * FF + f0);
                float4 v0 = __ldg(&xr[0]);
                float4 v1 = __ldg(&xr[1]);
                a0.x += wj * v0.x; a0.y += wj * v0.y; a0.z += wj * v0.z; a0.w += wj * v0.w;
                a1.x += wj * v1.x; a1.y += wj * v1.y; a1.z += wj * v1.z; a1.w += wj * v1.w;
            }
        }
        *(float4*)&y_s[la][f0]     = a0;
        *(float4*)&y_s[la][f0 + 4] = a1;
    }
    __syncthreads();

    int la0 = (t >> 3) * 4;
    ull acc[4][4];
    #pragma unroll
    for (int i = 0; i < 4; i++)
        #pragma unroll
        for (int p = 0; p < 4; p++) acc[i][p] = 0ULL;

    #pragma unroll 4
    for (int k4 = 0; k4 < FF / 4; k4++) {
        float4 yv[4];
        #pragma unroll
        for (int i = 0; i < 4; i++) yv[i] = *(const float4*)&y_s[la0 + i][k4 * 4];
        #pragma unroll
        for (int c = 0; c < 4; c++) {
            int k = k4 * 4 + c;
            ulonglong2 wa = *(const ulonglong2*)&sW[k][f0];
            ulonglong2 wb = *(const ulonglong2*)&sW[k][f0 + 4];
            #pragma unroll
            for (int i = 0; i < 4; i++) {
                float yc = (c == 0) ? yv[i].x : (c == 1) ? yv[i].y : (c == 2) ? yv[i].z : yv[i].w;
                ull y2 = pack2(yc, yc);
                acc[i][0] = fma2(y2, wa.x, acc[i][0]);
                acc[i][1] = fma2(y2, wa.y, acc[i][1]);
                acc[i][2] = fma2(y2, wb.x, acc[i][2]);
                acc[i][3] = fma2(y2, wb.y, acc[i][3]);
            }
        }
    }

    #pragma unroll
    for (int i = 0; i < 4; i++) {
        int a = base + la0 + i;
        if (a >= NN) break;
        float4 o0, o1;
        unpack2(acc[i][0], o0.x, o0.y);
        unpack2(acc[i][1], o0.z, o0.w);
        unpack2(acc[i][2], o1.x, o1.y);
        unpack2(acc[i][3], o1.z, o1.w);
        float* xo = xout + (size_t)a * FF + f0;
        *(float4*)(xo)     = o0;
        *(float4*)(xo + 4) = o1;
    }
}

// ---------------------------------------------------------------------------
// 4) crystal pooling + fc + out. One block (128 thr) per crystal.
// ---------------------------------------------------------------------------
__global__ __launch_bounds__(128) void pool_kernel(
    const float* __restrict__ xin,
    const int* __restrict__ cidx,
    const float* __restrict__ Wfc, const float* __restrict__ bfc,
    const float* __restrict__ Wout, const float* __restrict__ bout,
    float* __restrict__ out, float* __restrict__ hout)
{
    __shared__ float scrys[FF];
    __shared__ float sred[HF];
    int b    = blockIdx.x;
    int tid  = threadIdx.x;
    int f    = tid & 63;
    int half = tid >> 6;

    float acc = 0.f;
    for (int a = half * (NPB / 2); a < (half + 1) * (NPB / 2); a++) {
        int atom = __ldg(&cidx[b * NPB + a]);
        acc += xin[(size_t)atom * FF + f];
    }
    if (half == 1) scrys[f] = acc;
    __syncthreads();
    if (half == 0) scrys[f] = (scrys[f] + acc) * (1.0f / NPB);
    __syncthreads();

    float hv = bfc[tid];
    #pragma unroll
    for (int k = 0; k < FF; k++) hv += scrys[k] * Wfc[k * HF + tid];
    hv = softplusf(hv);
    if (hout) hout[(size_t)b * HF + tid] = hv;

    sred[tid] = hv * Wout[tid];
    __syncthreads();
    #pragma unroll
    for (int s = 64; s > 0; s >>= 1) {
        if (tid < s) sred[tid] += sred[tid + s];
        __syncthreads();
    }
    if (tid == 0) out[b] = sred[0] + bout[0];
}

// ---------------------------------------------------------------------------
extern "C" void kernel_launch(void* const* d_in, const int* in_sizes, int n_in,
                              void* d_out, int out_size)
{
    const float* atom_fea = (const float*)d_in[0];
    const float* nbr_fea  = (const float*)d_in[1];
    const int*   nbr_idx  = (const int*)  d_in[2];
    const int*   cidx     = (const int*)  d_in[3];
    // d_in[4] = pos : unused (Y0 is a constant)
    const float* W_emb = (const float*)d_in[5];
    const float* b_emb = (const float*)d_in[6];
    const float* Wr1   = (const float*)d_in[7];
    const float* br1   = (const float*)d_in[8];
    const float* Wr2   = (const float*)d_in[9];
    const float* br2   = (const float*)d_in[10];
    const float* Wtp   = (const float*)d_in[11];
    const float* W_fc  = (const float*)d_in[12];
    const float* b_fc  = (const float*)d_in[13];
    const float* W_out = (const float*)d_in[14];
    const float* b_out = (const float*)d_in[15];

    float* out_f = (float*)d_out;
    float* h_f   = (out_size >= BB + BB * HF) ? out_f + BB : nullptr;

    float* gx; cudaGetSymbolAddress((void**)&gx, g_x);
    float* gy; cudaGetSymbolAddress((void**)&gy, g_y);
    float* gw; cudaGetSymbolAddress((void**)&gw, g_w);

    embed_kernel<<<(NN + 15) / 16, 256>>>(atom_fea, W_emb, b_emb);
    edge_kernel<<<NM / EPB, 256>>>(nbr_fea, Wr1, br1, Wr2, br2);

    // layer ping-pong: x -> y -> x -> y
    conv_kernel<<<(NN + APB - 1) / APB, 256>>>(nbr_idx, Wtp + 0 * FF * FF, gw + 0 * (size_t)NM, gx, gy);
    conv_kernel<<<(NN + APB - 1) / APB, 256>>>(nbr_idx, Wtp + 1 * FF * FF, gw + 1 * (size_t)NM, gy, gx);
    conv_kernel<<<(NN + APB - 1) / APB, 256>>>(nbr_idx, Wtp + 2 * FF * FF, gw + 2 * (size_t)NM, gx, gy);

    pool_kernel<<<BB, 128>>>(gy, cidx, W_fc, b_fc, W_out, b_out, out_f, h_f);
}

// round 4
// speedup vs baseline: 1.8919x; 1.8919x over previous
#include <cuda_runtime.h>
#include <math.h>

#define NN   200000
#define MM   12
#define FF   64
#define NBR  41
#define NPAIRS 21         // 42 padded outputs = 21 f32x2 pairs (pad col 41 = 0)
#define ORIG 92
#define BB   2000
#define SHH  9
#define NC   3
#define HF   128
#define NM   (NN*MM)
#define NPB  (NN/BB)      // 100 atoms per crystal
#define APB  128          // atoms per conv block
// edge kernel geometry
#define EPB2   256        // edges per block
#define NWARPE 7
#define NTHRE  (NWARPE*32)   // 224
#define ESTRIDE 264          // padded e-tile row stride (floats)
// folded: c0 * alpha * (1/M)
#define WSCALE (0.28209479177387814f * 0.125f / 12.0f)

typedef unsigned long long ull;

// scratch (allocation-free rule: __device__ globals)
__device__ float g_x[(size_t)NN * FF];       // 51.2 MB
__device__ float g_y[(size_t)NN * FF];       // 51.2 MB
__device__ float g_w[(size_t)NC * NM];       // 28.8 MB

__device__ __forceinline__ float softplusf(float t) {
    // fast + stable: max(t,0) + log(1 + exp(-|t|)); arg of log in (1,2]
    return fmaxf(t, 0.0f) + __logf(1.0f + __expf(-fabsf(t)));
}

// ---- packed fp32x2 helpers (SASS FFMA2; ptxas won't emit these itself) ----
__device__ __forceinline__ ull pack2(float lo, float hi) {
    ull r; asm("mov.b64 %0, {%1, %2};" : "=l"(r) : "f"(lo), "f"(hi)); return r;
}
__device__ __forceinline__ void unpack2(ull v, float& lo, float& hi) {
    asm("mov.b64 {%0, %1}, %2;" : "=f"(lo), "=f"(hi) : "l"(v));
}
__device__ __forceinline__ ull fma2(ull a, ull b, ull c) {
    ull d; asm("fma.rn.f32x2 %0, %1, %2, %3;" : "=l"(d) : "l"(a), "l"(b), "l"(c));
    return d;
}

// ---------------------------------------------------------------------------
// 1) x = atom_fea @ W_emb + b_emb      (200000 x 92) @ (92 x 64)
// ---------------------------------------------------------------------------
__global__ __launch_bounds__(256) void embed_kernel(
    const float* __restrict__ af, const float* __restrict__ W,
    const float* __restrict__ b)
{
    __shared__ float sW[ORIG][FF];
    __shared__ float sb[FF];
    for (int i = threadIdx.x; i < ORIG * FF; i += 256) sW[i >> 6][i & 63] = W[i];
    if (threadIdx.x < FF) sb[threadIdx.x] = b[threadIdx.x];
    __syncthreads();

    int a  = blockIdx.x * 16 + (threadIdx.x >> 4);
    int f0 = (threadIdx.x & 15) * 4;
    if (a >= NN) return;

    const float4* row4 = (const float4*)(af + (size_t)a * ORIG);
    ull acc0 = pack2(sb[f0], sb[f0 + 1]);
    ull acc1 = pack2(sb[f0 + 2], sb[f0 + 3]);
    #pragma unroll
    for (int k4 = 0; k4 < ORIG / 4; k4++) {
        float4 v = row4[k4];
        int k = k4 * 4;
        #pragma unroll
        for (int c = 0; c < 4; c++) {
            float vc = (c == 0) ? v.x : (c == 1) ? v.y : (c == 2) ? v.z : v.w;
            ull v2 = pack2(vc, vc);
            const ull* wr = (const ull*)&sW[k + c][f0];
            acc0 = fma2(v2, wr[0], acc0);
            acc1 = fma2(v2, wr[1], acc1);
        }
    }
    float4 o;
    unpack2(acc0, o.x, o.y);
    unpack2(acc1, o.z, o.w);
    *(float4*)&g_x[(size_t)a * FF + f0] = o;
}

// ---------------------------------------------------------------------------
// 2) Edge radial scalars. Block: 256 edges, 7 warps. Warp = 3 output pairs
//    (21 pairs = 42 outputs, 1 zero pad). Thread = 8 edges x 3 pairs.
//    e tile staged transposed once, reused by all 3 layers.
//    Dynamic smem layout (bytes):
//      [0)        e_s   : 41 * ESTRIDE floats          (43296)
//      [43296)    w1_s  : 41 * 21 ull pairs            ( 6888)
//      [50184)    b1_s  : 21 ull                       (  168)
//      [50352)    w2_s  : 42 float                     (  168)
//      [50520)    b2_s  : 1 float (+pad to 50528)
//      [50528)    red   : 256 * 9 floats               ( 9216)   total 59744
// ---------------------------------------------------------------------------
#define EOF_W1  43296
#define EOF_B1  50184
#define EOF_W2  50352
#define EOF_B2  50520
#define EOF_RED 50528
#define E_SMEM  59744

__global__ __launch_bounds__(NTHRE, 3) void edge_kernel(
    const float* __restrict__ nbr_fea,
    const float* __restrict__ Wr1, const float* __restrict__ br1,
    const float* __restrict__ Wr2, const float* __restrict__ br2)
{
    extern __shared__ char dsm[];
    float* e_s  = (float*)(dsm);
    ull*   w1_s = (ull*)  (dsm + EOF_W1);
    ull*   b1_s = (ull*)  (dsm + EOF_B1);
    float* w2_s = (float*)(dsm + EOF_W2);
    float* b2_s = (float*)(dsm + EOF_B2);
    float* red  = (float*)(dsm + EOF_RED);

    const int t    = threadIdx.x;
    const int og   = t >> 5;            // warp id: pairs og*3 .. og*3+2
    const int lane = t & 31;
    const int le0  = lane * 8;          // this thread's 8 local edges
    const int p0   = og * 3;
    const size_t base = (size_t)blockIdx.x * EPB2;

    // ---- stage e tile transposed (once; reused by all 3 layers) ----
    const float* eg_ptr = nbr_fea + base * NBR;
    for (int idx = t; idx < EPB2 * NBR; idx += NTHRE) {
        int le = idx / NBR;
        int k  = idx - le * NBR;
        e_s[k * ESTRIDE + le] = __ldg(&eg_ptr[idx]);
    }

    #pragma unroll 1
    for (int l = 0; l < NC; l++) {
        __syncthreads();   // e staged (l=0); prev layer fully done (l>0)

        // ---- load layer-l weights ----
        const float* W1l = Wr1 + (size_t)l * NBR * NBR;
        for (int idx = t; idx < NBR * NPAIRS; idx += NTHRE) {
            int k = idx / NPAIRS, j = idx - k * NPAIRS;
            int j2 = 2 * j;
            float lo = __ldg(&W1l[k * NBR + j2]);
            float hi = (j2 + 1 < NBR) ? __ldg(&W1l[k * NBR + j2 + 1]) : 0.f;
            w1_s[k * NPAIRS + j] = pack2(lo, hi);
        }
        if (t < NPAIRS) {
            int j2 = 2 * t;
            float lo = __ldg(&br1[l * NBR + j2]);
            float hi = (j2 + 1 < NBR) ? __ldg(&br1[l * NBR + j2 + 1]) : 0.f;
            b1_s[t] = pack2(lo, hi);
        }
        if (t < 2 * NPAIRS)
            w2_s[t] = (t < NBR) ? __ldg(&Wr2[((size_t)l * NBR + t) * SHH]) : 0.f;
        if (t == 0) *b2_s = __ldg(&br2[l * SHH]);
        __syncthreads();

        // ---- k-loop: acc[edge 0..7][pair 0..2] ----
        ull acc[8][3];
        {
            ull b0 = b1_s[p0], b1 = b1_s[p0 + 1], b2 = b1_s[p0 + 2];
            #pragma unroll
            for (int i = 0; i < 8; i++) { acc[i][0] = b0; acc[i][1] = b1; acc[i][2] = b2; }
        }

        #pragma unroll 2
        for (int k = 0; k < NBR; k++) {
            const float* erow = e_s + k * ESTRIDE + le0;
            float4 a0 = *(const float4*)(erow);
            float4 a1 = *(const float4*)(erow + 4);
            ull bw0 = w1_s[k * NPAIRS + p0];
            ull bw1 = w1_s[k * NPAIRS + p0 + 1];
            ull bw2 = w1_s[k * NPAIRS + p0 + 2];
            float ev[8] = {a0.x, a0.y, a0.z, a0.w, a1.x, a1.y, a1.z, a1.w};
            #pragma unroll
            for (int i = 0; i < 8; i++) {
                ull a2 = pack2(ev[i], ev[i]);
                acc[i][0] = fma2(a2, bw0, acc[i][0]);
                acc[i][1] = fma2(a2, bw1, acc[i][1]);
                acc[i][2] = fma2(a2, bw2, acc[i][2]);
            }
        }

        // ---- epilogue: softplus . w2 partials into red ----
        float w2a = w2_s[p0 * 2],     w2b = w2_s[p0 * 2 + 1];
        float w2c = w2_s[p0 * 2 + 2], w2d = w2_s[p0 * 2 + 3];
        float w2e = w2_s[p0 * 2 + 4], w2f = w2_s[p0 * 2 + 5];
        #pragma unroll
        for (int i = 0; i < 8; i++) {
            float lo, hi, s;
            unpack2(acc[i][0], lo, hi);
            s  = softplusf(lo) * w2a + softplusf(hi) * w2b;
            unpack2(acc[i][1], lo, hi);
            s += softplusf(lo) * w2c + softplusf(hi) * w2d;
            unpack2(acc[i][2], lo, hi);
            s += softplusf(lo) * w2e + softplusf(hi) * w2f;
            red[(le0 + i) * 9 + og] = s;
        }
        __syncthreads();

        // ---- cross-warp reduce + store ----
        float b2v = *b2_s;
        for (int e = t; e < EPB2; e += NTHRE) {
            float s = b2v;
            #pragma unroll
            for (int o = 0; o < NWARPE; o++) s += red[e * 9 + o];
            g_w[(size_t)l * NM + base + e] = s * WSCALE;
        }
    }
}

// ---------------------------------------------------------------------------
// 3) Fused conv layer: y = weighted gather of xin, xout = y @ Wtp[l]
//    (exact round-2 code: known-good 124us/layer)
// ---------------------------------------------------------------------------
__global__ __launch_bounds__(256) void conv_kernel(
    const int* __restrict__ nbr_idx, const float* __restrict__ Wtp_l,
    const float* __restrict__ wl,
    const float* __restrict__ xin, float* __restrict__ xout)
{
    __shared__ float y_s[APB][68];
    __shared__ float sW[FF][FF];

    int t = threadIdx.x;
    for (int i = t; i < FF * FF; i += 256) sW[i >> 6][i & 63] = Wtp_l[i];

    int base = blockIdx.x * APB;
    int fg = t & 7;
    int f0 = fg * 8;

    #pragma unroll 1
    for (int r = 0; r < 4; r++) {
        int la = (t >> 3) + r * 32;
        int a  = base + la;
        float4 a0 = make_float4(0.f, 0.f, 0.f, 0.f);
        float4 a1 = make_float4(0.f, 0.f, 0.f, 0.f);
        if (a < NN) {
            #pragma unroll
            for (int j = 0; j < MM; j++) {
                int   s  = __ldg(&nbr_idx[a * MM + j]);
                float wj = __ldg(&wl[a * MM + j]);
                const float4* xr = (const float4*)(xin + (size_t)s * FF + f0);
                float4 v0 = __ldg(&xr[0]);
                float4 v1 = __ldg(&xr[1]);
                a0.x += wj * v0.x; a0.y += wj * v0.y; a0.z += wj * v0.z; a0.w += wj * v0.w;
                a1.x += wj * v1.x; a1.y += wj * v1.y; a1.z += wj * v1.z; a1.w += wj * v1.w;
            }
        }
        *(float4*)&y_s[la][f0]     = a0;
        *(float4*)&y_s[la][f0 + 4] = a1;
    }
    __syncthreads();

    int la0 = (t >> 3) * 4;
    ull acc[4][4];
    #pragma unroll
    for (int i = 0; i < 4; i++)
        #pragma unroll
        for (int p = 0; p < 4; p++) acc[i][p] = 0ULL;

    #pragma unroll 4
    for (int k4 = 0; k4 < FF / 4; k4++) {
        float4 yv[4];
        #pragma unroll
        for (int i = 0; i < 4; i++) yv[i] = *(const float4*)&y_s[la0 + i][k4 * 4];
        #pragma unroll
        for (int c = 0; c < 4; c++) {
            int k = k4 * 4 + c;
            ulonglong2 wa = *(const ulonglong2*)&sW[k][f0];
            ulonglong2 wb = *(const ulonglong2*)&sW[k][f0 + 4];
            #pragma unroll
            for (int i = 0; i < 4; i++) {
                float yc = (c == 0) ? yv[i].x : (c == 1) ? yv[i].y : (c == 2) ? yv[i].z : yv[i].w;
                ull y2 = pack2(yc, yc);
                acc[i][0] = fma2(y2, wa.x, acc[i][0]);
                acc[i][1] = fma2(y2, wa.y, acc[i][1]);
                acc[i][2] = fma2(y2, wb.x, acc[i][2]);
                acc[i][3] = fma2(y2, wb.y, acc[i][3]);
            }
        }
    }

    #pragma unroll
    for (int i = 0; i < 4; i++) {
        int a = base + la0 + i;
        if (a >= NN) break;
        float4 o0, o1;
        unpack2(acc[i][0], o0.x, o0.y);
        unpack2(acc[i][1], o0.z, o0.w);
        unpack2(acc[i][2], o1.x, o1.y);
        unpack2(acc[i][3], o1.z, o1.w);
        float* xo = xout + (size_t)a * FF + f0;
        *(float4*)(xo)     = o0;
        *(float4*)(xo + 4) = o1;
    }
}

// ---------------------------------------------------------------------------
// 4) crystal pooling + fc + out. One block (128 thr) per crystal.
// ---------------------------------------------------------------------------
__global__ __launch_bounds__(128) void pool_kernel(
    const float* __restrict__ xin,
    const int* __restrict__ cidx,
    const float* __restrict__ Wfc, const float* __restrict__ bfc,
    const float* __restrict__ Wout, const float* __restrict__ bout,
    float* __restrict__ out, float* __restrict__ hout)
{
    __shared__ float scrys[FF];
    __shared__ float sred[HF];
    int b    = blockIdx.x;
    int tid  = threadIdx.x;
    int f    = tid & 63;
    int half = tid >> 6;

    float acc = 0.f;
    for (int a = half * (NPB / 2); a < (half + 1) * (NPB / 2); a++) {
        int atom = __ldg(&cidx[b * NPB + a]);
        acc += xin[(size_t)atom * FF + f];
    }
    if (half == 1) scrys[f] = acc;
    __syncthreads();
    if (half == 0) scrys[f] = (scrys[f] + acc) * (1.0f / NPB);
    __syncthreads();

    float hv = bfc[tid];
    #pragma unroll
    for (int k = 0; k < FF; k++) hv += scrys[k] * Wfc[k * HF + tid];
    hv = fmaxf(hv, 0.0f) + log1pf(__expf(-fabsf(hv)));   // keep precise softplus here
    if (hout) hout[(size_t)b * HF + tid] = hv;

    sred[tid] = hv * Wout[tid];
    __syncthreads();
    #pragma unroll
    for (int s = 64; s > 0; s >>= 1) {
        if (tid < s) sred[tid] += sred[tid + s];
        __syncthreads();
    }
    if (tid == 0) out[b] = sred[0] + bout[0];
}

// ---------------------------------------------------------------------------
extern "C" void kernel_launch(void* const* d_in, const int* in_sizes, int n_in,
                              void* d_out, int out_size)
{
    const float* atom_fea = (const float*)d_in[0];
    const float* nbr_fea  = (const float*)d_in[1];
    const int*   nbr_idx  = (const int*)  d_in[2];
    const int*   cidx     = (const int*)  d_in[3];
    // d_in[4] = pos : unused (Y0 is a constant)
    const float* W_emb = (const float*)d_in[5];
    const float* b_emb = (const float*)d_in[6];
    const float* Wr1   = (const float*)d_in[7];
    const float* br1   = (const float*)d_in[8];
    const float* Wr2   = (const float*)d_in[9];
    const float* br2   = (const float*)d_in[10];
    const float* Wtp   = (const float*)d_in[11];
    const float* W_fc  = (const float*)d_in[12];
    const float* b_fc  = (const float*)d_in[13];
    const float* W_out = (const float*)d_in[14];
    const float* b_out = (const float*)d_in[15];

    float* out_f = (float*)d_out;
    float* h_f   = (out_size >= BB + BB * HF) ? out_f + BB : nullptr;

    float* gx; cudaGetSymbolAddress((void**)&gx, g_x);
    float* gy; cudaGetSymbolAddress((void**)&gy, g_y);
    float* gw; cudaGetSymbolAddress((void**)&gw, g_w);

    static int smem_set = 0;
    if (!smem_set) {
        cudaFuncSetAttribute(edge_kernel,
                             cudaFuncAttributeMaxDynamicSharedMemorySize, E_SMEM);
        smem_set = 1;
    }

    embed_kernel<<<(NN + 15) / 16, 256>>>(atom_fea, W_emb, b_emb);
    edge_kernel<<<NM / EPB2, NTHRE, E_SMEM>>>(nbr_fea, Wr1, br1, Wr2, br2);

    // layer ping-pong: x -> y -> x -> y
    conv_kernel<<<(NN + APB - 1) / APB, 256>>>(nbr_idx, Wtp + 0 * FF * FF, gw + 0 * (size_t)NM, gx, gy);
    conv_kernel<<<(NN + APB - 1) / APB, 256>>>(nbr_idx, Wtp + 1 * FF * FF, gw + 1 * (size_t)NM, gy, gx);
    conv_kernel<<<(NN + APB - 1) / APB, 256>>>(nbr_idx, Wtp + 2 * FF * FF, gw + 2 * (size_t)NM, gx, gy);

    pool_kernel<<<BB, 128>>>(gy, cidx, W_fc, b_fc, W_out, b_out, out_f, h_f);
}